// round 2
// baseline (speedup 1.0000x reference)
#include <cuda_runtime.h>
#include <math.h>
#include <float.h>

// Problem constants
#define B_   4
#define T_   2048
#define C_   1024
#define H_   16
#define D_   64
#define BT_  (B_*T_)           // 8192
#define F3_  (3*C_)            // 3072

// Scratch (static device globals: alloc-free, graph-safe)
__device__ float g_qkv[(size_t)BT_ * F3_];        // [B*T, 3C]
__device__ float g_q[(size_t)B_*H_*T_*D_];        // [B,H,T,D]
__device__ float g_k[(size_t)B_*H_*T_*D_];
__device__ float g_v[(size_t)B_*H_*T_*D_];
__device__ float g_y[(size_t)BT_ * C_];           // [B,T,C]

// ---------------------------------------------------------------------------
// SGEMM: C[M,N] = A[M,K] @ B[K,N], row-major, fp32. Tiles 128x128, BK=8,
// 256 threads, 8x8 micro-tile per thread. Dims must divide tiles (they do).
// ---------------------------------------------------------------------------
__global__ __launch_bounds__(256) void sgemm_k(
    const float* __restrict__ A, const float* __restrict__ B,
    float* __restrict__ C, int M, int N, int K)
{
    __shared__ float As[8][128];
    __shared__ float Bs[8][128];

    const int tid = threadIdx.x;
    const int bm = blockIdx.y * 128;
    const int bn = blockIdx.x * 128;

    const int a_row = tid >> 1;           // 0..127
    const int a_col = (tid & 1) * 4;      // 0 or 4
    const int b_row = tid >> 5;           // 0..7
    const int b_col = (tid & 31) * 4;     // 0..124

    const float* Aptr = A + (size_t)(bm + a_row) * K + a_col;
    const float* Bptr = B + (size_t)b_row * N + bn + b_col;

    const int tm = (tid >> 4) * 8;        // 0..120
    const int tn = (tid & 15) * 8;        // 0..120

    float acc[8][8];
#pragma unroll
    for (int i = 0; i < 8; ++i)
#pragma unroll
        for (int j = 0; j < 8; ++j) acc[i][j] = 0.f;

    for (int k0 = 0; k0 < K; k0 += 8) {
        float4 av = *(const float4*)Aptr;  Aptr += 8;
        float4 bv = *(const float4*)Bptr;  Bptr += (size_t)8 * N;

        As[a_col + 0][a_row] = av.x;
        As[a_col + 1][a_row] = av.y;
        As[a_col + 2][a_row] = av.z;
        As[a_col + 3][a_row] = av.w;
        *(float4*)&Bs[b_row][b_col] = bv;
        __syncthreads();

#pragma unroll
        for (int kk = 0; kk < 8; ++kk) {
            float4 a0 = *(const float4*)&As[kk][tm];
            float4 a1 = *(const float4*)&As[kk][tm + 4];
            float4 b0 = *(const float4*)&Bs[kk][tn];
            float4 b1 = *(const float4*)&Bs[kk][tn + 4];
            float ar[8] = {a0.x,a0.y,a0.z,a0.w,a1.x,a1.y,a1.z,a1.w};
            float br[8] = {b0.x,b0.y,b0.z,b0.w,b1.x,b1.y,b1.z,b1.w};
#pragma unroll
            for (int i = 0; i < 8; ++i)
#pragma unroll
                for (int j = 0; j < 8; ++j)
                    acc[i][j] = fmaf(ar[i], br[j], acc[i][j]);
        }
        __syncthreads();
    }

#pragma unroll
    for (int i = 0; i < 8; ++i) {
        float* Crow = C + (size_t)(bm + tm + i) * N + bn + tn;
        float4 c0 = {acc[i][0], acc[i][1], acc[i][2], acc[i][3]};
        float4 c1 = {acc[i][4], acc[i][5], acc[i][6], acc[i][7]};
        *(float4*)(Crow)     = c0;
        *(float4*)(Crow + 4) = c1;
    }
}

// ---------------------------------------------------------------------------
// RoPE + split + transpose: qkv[B,T,3C] -> q,k (roped) and v in [B,H,T,D]
// One thread per (b,t,h,pair).
// ---------------------------------------------------------------------------
__global__ void rope_split_k(const float* __restrict__ qkv,
                             float* __restrict__ q,
                             float* __restrict__ k,
                             float* __restrict__ v)
{
    const int idx = blockIdx.x * blockDim.x + threadIdx.x;  // B*T*H*32 total
    const int p = idx & 31;
    const int h = (idx >> 5) & 15;
    const int t = (idx >> 9) & 2047;
    const int b = idx >> 20;

    const float* base = qkv + (size_t)(b * T_ + t) * F3_;
    const int c = h * D_ + 2 * p;

    const float q1 = base[c],          q2 = base[c + 1];
    const float k1 = base[C_ + c],     k2 = base[C_ + c + 1];
    const float v1 = base[2*C_ + c],   v2 = base[2*C_ + c + 1];

    // inv_freq = 10000^(-2p/64) = exp2(-(2p/64) * log2(10000))
    const float inv = exp2f(-(float)(2 * p) * (13.287712379549449f / 64.f));
    const float ang = (float)t * inv;
    float sn, cs;
    sincosf(ang, &sn, &cs);

    const size_t o = ((size_t)((b * H_ + h) * T_ + t)) * D_ + 2 * p;
    q[o]     = q1 * cs - q2 * sn;
    q[o + 1] = q1 * sn + q2 * cs;
    k[o]     = k1 * cs - k2 * sn;
    k[o + 1] = k1 * sn + k2 * cs;
    v[o]     = v1;
    v[o + 1] = v2;
}

// ---------------------------------------------------------------------------
// Causal flash attention, fp32. One block per (q_tile=64 rows, head, batch).
// 256 threads as 16x16 grid, 4x4 micro-tiles. K tile padded (stride 65) for
// conflict-free fragment loads; P aliases the K buffer after S is computed.
// Writes y in [B,T,H,D] (== [B,T,C]) for the projection GEMM.
// ---------------------------------------------------------------------------
#define ATT_SMEM ((64*64 + 64*65 + 64*64) * 4)   // 49408 bytes

__global__ __launch_bounds__(256) void attn_k(
    const float* __restrict__ Q, const float* __restrict__ K,
    const float* __restrict__ V, float* __restrict__ Y)
{
    extern __shared__ float sm[];
    float* Qs = sm;               // [64][64]
    float* KP = sm + 64*64;       // [64][65]  (K tile, later P tile)
    float* Vs = KP + 64*65;       // [64][64]

    const int qt = blockIdx.x;    // 0..31
    const int h  = blockIdx.y;
    const int b  = blockIdx.z;
    const int bh = b * H_ + h;

    const float* Qp = Q + (size_t)bh * T_ * D_;
    const float* Kp = K + (size_t)bh * T_ * D_;
    const float* Vp = V + (size_t)bh * T_ * D_;

    const int tid = threadIdx.x;
    const int tm = tid >> 4;      // 0..15 -> rows tm*4..tm*4+3
    const int tn = tid & 15;      // 0..15 -> cols tn*4..tn*4+3
    const int q0 = qt * 64;

    const int lr = tid >> 4;              // loader row within pass
    const int lc = (tid & 15) * 4;        // loader col (float4)

    // Load Q tile
#pragma unroll
    for (int ps = 0; ps < 4; ++ps) {
        int r = ps * 16 + lr;
        *(float4*)&Qs[r * 64 + lc] = *(const float4*)&Qp[(size_t)(q0 + r) * D_ + lc];
    }

    float m[4], l[4], o[4][4];
#pragma unroll
    for (int i = 0; i < 4; ++i) {
        m[i] = -INFINITY; l[i] = 0.f;
#pragma unroll
        for (int j = 0; j < 4; ++j) o[i][j] = 0.f;
    }

    for (int kt = 0; kt <= qt; ++kt) {
        const int k0 = kt * 64;
        __syncthreads();   // previous iteration done with KP(=P) and Vs

        // Load K (padded stride 65) and V
#pragma unroll
        for (int ps = 0; ps < 4; ++ps) {
            int r = ps * 16 + lr;
            float4 kv = *(const float4*)&Kp[(size_t)(k0 + r) * D_ + lc];
            KP[r * 65 + lc + 0] = kv.x;
            KP[r * 65 + lc + 1] = kv.y;
            KP[r * 65 + lc + 2] = kv.z;
            KP[r * 65 + lc + 3] = kv.w;
            *(float4*)&Vs[r * 64 + lc] = *(const float4*)&Vp[(size_t)(k0 + r) * D_ + lc];
        }
        __syncthreads();

        // S = Q @ K^T
        float s[4][4];
#pragma unroll
        for (int i = 0; i < 4; ++i)
#pragma unroll
            for (int j = 0; j < 4; ++j) s[i][j] = 0.f;

#pragma unroll 8
        for (int d = 0; d < 64; ++d) {
            float a0 = Qs[(tm*4 + 0) * 64 + d];
            float a1 = Qs[(tm*4 + 1) * 64 + d];
            float a2 = Qs[(tm*4 + 2) * 64 + d];
            float a3 = Qs[(tm*4 + 3) * 64 + d];
            float b0 = KP[(tn*4 + 0) * 65 + d];
            float b1 = KP[(tn*4 + 1) * 65 + d];
            float b2 = KP[(tn*4 + 2) * 65 + d];
            float b3 = KP[(tn*4 + 3) * 65 + d];
            s[0][0] = fmaf(a0,b0,s[0][0]); s[0][1] = fmaf(a0,b1,s[0][1]);
            s[0][2] = fmaf(a0,b2,s[0][2]); s[0][3] = fmaf(a0,b3,s[0][3]);
            s[1][0] = fmaf(a1,b0,s[1][0]); s[1][1] = fmaf(a1,b1,s[1][1]);
            s[1][2] = fmaf(a1,b2,s[1][2]); s[1][3] = fmaf(a1,b3,s[1][3]);
            s[2][0] = fmaf(a2,b0,s[2][0]); s[2][1] = fmaf(a2,b1,s[2][1]);
            s[2][2] = fmaf(a2,b2,s[2][2]); s[2][3] = fmaf(a2,b3,s[2][3]);
            s[3][0] = fmaf(a3,b0,s[3][0]); s[3][1] = fmaf(a3,b1,s[3][1]);
            s[3][2] = fmaf(a3,b2,s[3][2]); s[3][3] = fmaf(a3,b3,s[3][3]);
        }

        const float scale = 0.125f;   // 1/sqrt(64)
#pragma unroll
        for (int i = 0; i < 4; ++i)
#pragma unroll
            for (int j = 0; j < 4; ++j) s[i][j] *= scale;

        if (kt == qt) {   // diagonal tile: causal mask
#pragma unroll
            for (int i = 0; i < 4; ++i)
#pragma unroll
                for (int j = 0; j < 4; ++j)
                    if (k0 + tn*4 + j > q0 + tm*4 + i) s[i][j] = -INFINITY;
        }

        // Row max over the 16 tn lanes
        float rmax[4];
#pragma unroll
        for (int i = 0; i < 4; ++i)
            rmax[i] = fmaxf(fmaxf(s[i][0], s[i][1]), fmaxf(s[i][2], s[i][3]));
#pragma unroll
        for (int off = 8; off >= 1; off >>= 1)
#pragma unroll
            for (int i = 0; i < 4; ++i)
                rmax[i] = fmaxf(rmax[i], __shfl_xor_sync(0xffffffffu, rmax[i], off));

        float alpha[4], rsum[4];
#pragma unroll
        for (int i = 0; i < 4; ++i) {
            float mn = fmaxf(m[i], rmax[i]);
            alpha[i] = __expf(m[i] - mn);
            m[i] = mn;
            rsum[i] = 0.f;
#pragma unroll
            for (int j = 0; j < 4; ++j) {
                s[i][j] = __expf(s[i][j] - mn);
                rsum[i] += s[i][j];
            }
        }
#pragma unroll
        for (int off = 8; off >= 1; off >>= 1)
#pragma unroll
            for (int i = 0; i < 4; ++i)
                rsum[i] += __shfl_xor_sync(0xffffffffu, rsum[i], off);

#pragma unroll
        for (int i = 0; i < 4; ++i) {
            l[i] = l[i] * alpha[i] + rsum[i];
#pragma unroll
            for (int j = 0; j < 4; ++j) o[i][j] *= alpha[i];
        }

        __syncthreads();   // everyone done reading KP as K
        // Write P into KP
#pragma unroll
        for (int i = 0; i < 4; ++i)
#pragma unroll
            for (int j = 0; j < 4; ++j)
                KP[(tm*4 + i) * 65 + tn*4 + j] = s[i][j];
        __syncthreads();

        // O += P @ V
#pragma unroll 8
        for (int jj = 0; jj < 64; ++jj) {
            float p0 = KP[(tm*4 + 0) * 65 + jj];
            float p1 = KP[(tm*4 + 1) * 65 + jj];
            float p2 = KP[(tm*4 + 2) * 65 + jj];
            float p3 = KP[(tm*4 + 3) * 65 + jj];
            float4 vv = *(const float4*)&Vs[jj * 64 + tn*4];
            o[0][0] = fmaf(p0, vv.x, o[0][0]); o[0][1] = fmaf(p0, vv.y, o[0][1]);
            o[0][2] = fmaf(p0, vv.z, o[0][2]); o[0][3] = fmaf(p0, vv.w, o[0][3]);
            o[1][0] = fmaf(p1, vv.x, o[1][0]); o[1][1] = fmaf(p1, vv.y, o[1][1]);
            o[1][2] = fmaf(p1, vv.z, o[1][2]); o[1][3] = fmaf(p1, vv.w, o[1][3]);
            o[2][0] = fmaf(p2, vv.x, o[2][0]); o[2][1] = fmaf(p2, vv.y, o[2][1]);
            o[2][2] = fmaf(p2, vv.z, o[2][2]); o[2][3] = fmaf(p2, vv.w, o[2][3]);
            o[3][0] = fmaf(p3, vv.x, o[3][0]); o[3][1] = fmaf(p3, vv.y, o[3][1]);
            o[3][2] = fmaf(p3, vv.z, o[3][2]); o[3][3] = fmaf(p3, vv.w, o[3][3]);
        }
    }

    // Epilogue: normalize, write y as [B,T,H,D] == [B,T,C]
#pragma unroll
    for (int i = 0; i < 4; ++i) {
        const float inv = 1.f / l[i];
        const int t = q0 + tm*4 + i;
        float* Yrow = Y + ((size_t)(b * T_ + t) * H_ + h) * D_ + tn*4;
#pragma unroll
        for (int j = 0; j < 4; ++j) Yrow[j] = o[i][j] * inv;
    }
}

// ---------------------------------------------------------------------------
extern "C" void kernel_launch(void* const* d_in, const int* in_sizes, int n_in,
                              void* d_out, int out_size)
{
    const float* x      = (const float*)d_in[0];   // [B,T,C]
    const float* W_attn = (const float*)d_in[1];   // [C,3C]
    const float* W_proj = (const float*)d_in[2];   // [C,C]
    float* out = (float*)d_out;                    // [B,T,C]

    float *qkv, *q, *k, *v, *y;
    cudaGetSymbolAddress((void**)&qkv, g_qkv);
    cudaGetSymbolAddress((void**)&q,   g_q);
    cudaGetSymbolAddress((void**)&k,   g_k);
    cudaGetSymbolAddress((void**)&v,   g_v);
    cudaGetSymbolAddress((void**)&y,   g_y);

    cudaFuncSetAttribute(attn_k, cudaFuncAttributeMaxDynamicSharedMemorySize, ATT_SMEM);

    // 1) QKV GEMM: [8192,1024] @ [1024,3072]
    {
        dim3 grid(F3_ / 128, BT_ / 128);
        sgemm_k<<<grid, 256>>>(x, W_attn, qkv, BT_, F3_, C_);
    }
    // 2) RoPE + split/transpose
    {
        int total = B_ * T_ * H_ * (D_ / 2);   // 4,194,304
        rope_split_k<<<total / 256, 256>>>(qkv, q, k, v);
    }
    // 3) Causal flash attention
    {
        dim3 grid(T_ / 64, H_, B_);
        attn_k<<<grid, 256, ATT_SMEM>>>(q, k, v, y);
    }
    // 4) Projection GEMM: [8192,1024] @ [1024,1024]
    {
        dim3 grid(C_ / 128, BT_ / 128);
        sgemm_k<<<grid, 256>>>(y, W_proj, out, BT_, C_, C_);
    }
}